// round 6
// baseline (speedup 1.0000x reference)
#include <cuda_runtime.h>
#include <cuda_bf16.h>
#include <cstdint>

#define NTOK 4096
#define HID  1024
#define NEXP 64
#define TOPK 8
#define IDIM 768
#define FLAT (NTOK*TOPK)
#define BM   128
#define MPAD 40960
#define MAXTILES 320

// ---------------- scratch ----------------
static __device__ __nv_bfloat16 g_xh[(size_t)NTOK * HID];
static __device__ __nv_bfloat16 g_xl[(size_t)NTOK * HID];
static __device__ __nv_bfloat16 g_wgh[(size_t)NEXP * 2 * IDIM * HID];
static __device__ __nv_bfloat16 g_wgl[(size_t)NEXP * 2 * IDIM * HID];
static __device__ __nv_bfloat16 g_wdh[(size_t)NEXP * HID * IDIM];
static __device__ __nv_bfloat16 g_wdl[(size_t)NEXP * HID * IDIM];
static __device__ __nv_bfloat16 g_ih[(size_t)MPAD * IDIM];
static __device__ __nv_bfloat16 g_il[(size_t)MPAD * IDIM];
static __device__ float g_y2[(size_t)MPAD * HID];
static __device__ float g_topkw[FLAT];
static __device__ int   g_flatexp[FLAT];
static __device__ int   g_invperm[FLAT];
static __device__ int   g_rowtok[MPAD];
static __device__ int   g_counts[NEXP];
static __device__ int   g_ctr[NEXP];
static __device__ int   g_offpad[NEXP];
static __device__ int   g_tile_e[MAXTILES];
static __device__ int   g_tile_r0[MAXTILES];
static __device__ int   g_ntiles;
static __device__ __align__(16) uint4 g_zero4 = {0u, 0u, 0u, 0u};

// ---------------- helpers ----------------
__device__ __forceinline__ uint32_t smem_u32(const void* p) {
    uint32_t a;
    asm("{ .reg .u64 t; cvta.to.shared.u64 t, %1; cvt.u32.u64 %0, t; }" : "=r"(a) : "l"(p));
    return a;
}
#define CP16(d, s) \
    asm volatile("cp.async.cg.shared.global [%0], [%1], 16;" :: "r"(d), "l"(s) : "memory")
#define CP_COMMIT() asm volatile("cp.async.commit_group;" ::: "memory")
#define CP_WAIT1()  asm volatile("cp.async.wait_group 1;" ::: "memory")

__device__ __forceinline__ void ldsm_x4(uint32_t (&r)[4], uint32_t addr) {
    asm volatile("ldmatrix.sync.aligned.m8n8.x4.shared.b16 {%0,%1,%2,%3}, [%4];"
        : "=r"(r[0]), "=r"(r[1]), "=r"(r[2]), "=r"(r[3]) : "r"(addr));
}
__device__ __forceinline__ void mma16816(float (&d)[4], const uint32_t (&a)[4], const uint32_t (&b)[2]) {
    asm volatile("mma.sync.aligned.m16n8k16.row.col.f32.bf16.bf16.f32 "
        "{%0,%1,%2,%3}, {%4,%5,%6,%7}, {%8,%9}, {%0,%1,%2,%3};"
        : "+f"(d[0]), "+f"(d[1]), "+f"(d[2]), "+f"(d[3])
        : "r"(a[0]), "r"(a[1]), "r"(a[2]), "r"(a[3]), "r"(b[0]), "r"(b[1]));
}

// fp32x8 -> bf16 hi/lo split
__device__ __forceinline__ void cvt8(const float4 f0, const float4 f1, uint4& H, uint4& L) {
    __nv_bfloat162 h;
    h = __float22bfloat162_rn(make_float2(f0.x, f0.y)); uint32_t u0 = *(uint32_t*)&h;
    h = __float22bfloat162_rn(make_float2(f0.z, f0.w)); uint32_t u1 = *(uint32_t*)&h;
    h = __float22bfloat162_rn(make_float2(f1.x, f1.y)); uint32_t u2 = *(uint32_t*)&h;
    h = __float22bfloat162_rn(make_float2(f1.z, f1.w)); uint32_t u3 = *(uint32_t*)&h;
    H = make_uint4(u0, u1, u2, u3);
    float l0 = f0.x - __uint_as_float(u0 << 16);
    float l1 = f0.y - __uint_as_float(u0 & 0xFFFF0000u);
    float l2 = f0.z - __uint_as_float(u1 << 16);
    float l3 = f0.w - __uint_as_float(u1 & 0xFFFF0000u);
    float l4 = f1.x - __uint_as_float(u2 << 16);
    float l5 = f1.y - __uint_as_float(u2 & 0xFFFF0000u);
    float l6 = f1.z - __uint_as_float(u3 << 16);
    float l7 = f1.w - __uint_as_float(u3 & 0xFFFF0000u);
    h = __float22bfloat162_rn(make_float2(l0, l1)); uint32_t v0 = *(uint32_t*)&h;
    h = __float22bfloat162_rn(make_float2(l2, l3)); uint32_t v1 = *(uint32_t*)&h;
    h = __float22bfloat162_rn(make_float2(l4, l5)); uint32_t v2 = *(uint32_t*)&h;
    h = __float22bfloat162_rn(make_float2(l6, l7)); uint32_t v3 = *(uint32_t*)&h;
    L = make_uint4(v0, v1, v2, v3);
}

// ---------------- conversion kernels ----------------
__global__ void cvt_kernel(const float* __restrict__ src, int mode, long n8) {
    long i = (long)blockIdx.x * 256 + threadIdx.x;
    if (i >= n8) return;
    __nv_bfloat16 *dh, *dl;
    if (mode == 0)      { dh = g_xh;  dl = g_xl;  }
    else if (mode == 1) { dh = g_wgh; dl = g_wgl; }
    else                { dh = g_wdh; dl = g_wdl; }
    float4 f0 = ((const float4*)src)[2 * i];
    float4 f1 = ((const float4*)src)[2 * i + 1];
    uint4 H, L; cvt8(f0, f1, H, L);
    ((uint4*)dh)[i] = H;
    ((uint4*)dl)[i] = L;
}

// ---------------- small kernels ----------------
__global__ void init_kernel() {
    int i = threadIdx.x;
    if (i < NEXP) { g_counts[i] = 0; g_ctr[i] = 0; }
}

#define RT 8
__global__ void router_kernel(const float* __restrict__ x, const float* __restrict__ gate) {
    __shared__ float xs[RT][HID];
    __shared__ float lg[RT][NEXP];
    int t0 = blockIdx.x * RT;
    int tid = threadIdx.x;  // 256
    const float4* xsrc = (const float4*)(x + (size_t)t0 * HID);
    for (int i = tid; i < RT * HID / 4; i += 256) ((float4*)&xs[0][0])[i] = xsrc[i];
    __syncthreads();
    int tt = tid >> 5, lane = tid & 31;
    #pragma unroll
    for (int g = 0; g < 2; g++) {
        int e = g * 32 + lane;
        const float* gp = gate + (size_t)e * HID;
        float s = 0.f;
        #pragma unroll 4
        for (int k = 0; k < HID; k += 4) {
            float4 gv = *(const float4*)(gp + k);
            s += xs[tt][k] * gv.x + xs[tt][k+1] * gv.y + xs[tt][k+2] * gv.z + xs[tt][k+3] * gv.w;
        }
        lg[tt][e] = s;
    }
    __syncthreads();
    if (tid < RT) {
        int t = t0 + tid;
        float mx = lg[tid][0];
        #pragma unroll
        for (int e = 1; e < NEXP; e++) mx = fmaxf(mx, lg[tid][e]);
        unsigned long long taken = 0ull;
        float wsum = 0.f;
        int sel[TOPK]; float wv[TOPK];
        for (int k = 0; k < TOPK; k++) {
            int best = 0; float bv = -1e30f;
            for (int e = 0; e < NEXP; e++) {
                float v = lg[tid][e];
                if (!((taken >> e) & 1ull) && v > bv) { bv = v; best = e; }
            }
            taken |= 1ull << best;
            sel[k] = best;
            float w = expf(lg[tid][best] - mx);
            wv[k] = w; wsum += w;
            atomicAdd(&g_counts[best], 1);
        }
        float inv = 1.f / wsum;
        for (int k = 0; k < TOPK; k++) {
            g_topkw[t * TOPK + k]   = wv[k] * inv;
            g_flatexp[t * TOPK + k] = sel[k];
        }
    }
}

__global__ void meta_kernel() {
    if (threadIdx.x != 0) return;
    int nt = 0, cum = 0;
    for (int e = 0; e < NEXP; e++) {
        g_offpad[e] = cum;
        int c = g_counts[e];
        int t = (c + BM - 1) / BM;
        for (int j = 0; j < t; j++) { g_tile_e[nt] = e; g_tile_r0[nt] = cum + j * BM; nt++; }
        cum += t * BM;
    }
    g_ntiles = nt;
}

__global__ void fill_kernel() {
    int i = blockIdx.x * 256 + threadIdx.x;
    if (i < MPAD) g_rowtok[i] = -1;
}

__global__ void scatter_kernel() {
    int i = blockIdx.x * 256 + threadIdx.x;
    if (i >= FLAT) return;
    int e = g_flatexp[i];
    int dest = g_offpad[e] + atomicAdd(&g_ctr[e], 1);
    g_rowtok[dest] = i >> 3;
    g_invperm[i] = dest;
}

// ---------------- grouped GEMM: cp.async 3-stage, KC=32, 96KB smem, 2 CTA/SM ----------------
// CTA: 256 thr = 8 warps (2x4), tile M=128 x N=128, warp tile 64x32.
// Stage = Ah|Al|Bh|Bl, each [128 rows][32 bf16] = 8KB (64B rows, 4x16B chunks,
// chunk ^= (row>>1)&3 swizzle). 3 stages x 32KB = 96KB dynamic smem.

#define STG_SZ 32768
#define OFF_AL 8192
#define OFF_BH 16384
#define OFF_BL 24576
#define SMEM_BYTES (3 * STG_SZ)

template<bool FUSED>
__global__ void __launch_bounds__(256, 2) moe_gemm() {
    constexpr int KDIM = FUSED ? HID : IDIM;    // 1024 / 768
    constexpr int NK   = KDIM / 32;             // 32 / 24
    int tile = blockIdx.x;
    if (tile >= g_ntiles) return;
    int e = g_tile_e[tile], row0 = g_tile_r0[tile], nb = blockIdx.y;

    extern __shared__ __align__(128) char smem[];
    uint32_t sb = smem_u32(smem);
    int tid = threadIdx.x, lane = tid & 31, wid = tid >> 5;
    int wm = wid >> 2, wn = wid & 3;

    // -------- copy mapping: j in {0,1}: row = tid/4 + 64*j, chunk = tid&3
    int ch = tid & 3;
    uint32_t soff[2];
    size_t aoff[2], boff[2];                    // element offsets into (xh,xl)/(wh,wl)
    const __nv_bfloat16* WH = FUSED ? g_wgh : g_wdh;
    const __nv_bfloat16* WL = FUSED ? g_wgl : g_wdl;
    const __nv_bfloat16* AH = FUSED ? g_xh : g_ih;
    const __nv_bfloat16* AL = FUSED ? g_xl : g_il;
    #pragma unroll
    for (int j = 0; j < 2; j++) {
        int r = (tid >> 2) + 64 * j;
        soff[j] = (uint32_t)(r * 64 + ((ch ^ ((r >> 1) & 3)) << 4));
        if (FUSED) {
            int tok = g_rowtok[row0 + r];
            aoff[j] = (tok >= 0) ? ((size_t)tok * HID + ch * 8) : (size_t)-1;
        } else {
            aoff[j] = (size_t)(row0 + r) * IDIM + ch * 8;
        }
        int wrow = FUSED ? ((r < 64) ? nb * 64 + r : IDIM + nb * 64 + (r - 64))
                         : nb * 128 + r;
        boff[j] = (size_t)e * (size_t)(FUSED ? 2 * IDIM : HID) * KDIM
                  + (size_t)wrow * KDIM + ch * 8;
    }

    auto issue = [&](int kt) {
        uint32_t st = sb + (uint32_t)((kt % 3) * STG_SZ);
        size_t ko = (size_t)kt * 32;   // elements per K-tile
        #pragma unroll
        for (int j = 0; j < 2; j++) {
            const void *sh, *sl;
            if (FUSED && aoff[j] == (size_t)-1) {
                sh = &g_zero4; sl = &g_zero4;
            } else {
                sh = AH + aoff[j] + ko; sl = AL + aoff[j] + ko;
            }
            CP16(st + soff[j],          sh);
            CP16(st + OFF_AL + soff[j], sl);
            CP16(st + OFF_BH + soff[j], WH + boff[j] + ko);
            CP16(st + OFF_BL + soff[j], WL + boff[j] + ko);
        }
        CP_COMMIT();
    };

    float acc[4][4][4];
    #pragma unroll
    for (int a = 0; a < 4; a++)
        #pragma unroll
        for (int b = 0; b < 4; b++)
            #pragma unroll
            for (int c = 0; c < 4; c++) acc[a][b][c] = 0.f;

    issue(0); issue(1);

    #pragma unroll 1
    for (int kt = 0; kt < NK; kt++) {
        CP_WAIT1();
        __syncthreads();
        if (kt + 2 < NK) issue(kt + 2);
        else CP_COMMIT();
        uint32_t st = sb + (uint32_t)((kt % 3) * STG_SZ);

        #pragma unroll
        for (int kq = 0; kq < 2; kq++) {
            uint32_t aH[4][4], aL[4][4], bH[4][2], bL[4][2];
            #pragma unroll
            for (int mt = 0; mt < 4; mt++) {
                int row = wm * 64 + mt * 16 + (lane & 15);
                int c = 2 * kq + (lane >> 4);
                uint32_t ad = (uint32_t)(row * 64 + ((c ^ ((row >> 1) & 3)) << 4));
                ldsm_x4(aH[mt], st + ad);
                ldsm_x4(aL[mt], st + OFF_AL + ad);
            }
            #pragma unroll
            for (int np = 0; np < 2; np++) {
                int row = wn * 32 + np * 16 + (lane & 7) + ((lane >> 4) << 3);
                int c = 2 * kq + ((lane >> 3) & 1);
                uint32_t bd = (uint32_t)(row * 64 + ((c ^ ((row >> 1) & 3)) << 4));
                uint32_t t4[4];
                ldsm_x4(t4, st + OFF_BH + bd);
                bH[2*np][0] = t4[0]; bH[2*np][1] = t4[1];
                bH[2*np+1][0] = t4[2]; bH[2*np+1][1] = t4[3];
                ldsm_x4(t4, st + OFF_BL + bd);
                bL[2*np][0] = t4[0]; bL[2*np][1] = t4[1];
                bL[2*np+1][0] = t4[2]; bL[2*np+1][1] = t4[3];
            }
            #pragma unroll
            for (int mt = 0; mt < 4; mt++)
                #pragma unroll
                for (int nt = 0; nt < 4; nt++) {
                    mma16816(acc[mt][nt], aH[mt], bH[nt]);
                    mma16816(acc[mt][nt], aH[mt], bL[nt]);
                    mma16816(acc[mt][nt], aL[mt], bH[nt]);
                }
        }
    }
    __syncthreads();   // all frag reads done; smem reusable

    if (FUSED) {
        float* sUp = (float*)smem;   // [128][64] f32 = 32KB
        if (wn >= 2) {
            #pragma unroll
            for (int mt = 0; mt < 4; mt++)
                #pragma unroll
                for (int nt = 0; nt < 4; nt++) {
                    int m = wm * 64 + mt * 16 + (lane >> 2);
                    int c = (wn - 2) * 32 + nt * 8 + (lane & 3) * 2;
                    sUp[m * 64 + c]           = acc[mt][nt][0];
                    sUp[m * 64 + c + 1]       = acc[mt][nt][1];
                    sUp[(m + 8) * 64 + c]     = acc[mt][nt][2];
                    sUp[(m + 8) * 64 + c + 1] = acc[mt][nt][3];
                }
        }
        __syncthreads();
        if (wn < 2) {
            #pragma unroll
            for (int mt = 0; mt < 4; mt++)
                #pragma unroll
                for (int nt = 0; nt < 4; nt++) {
                    int m = wm * 64 + mt * 16 + (lane >> 2);
                    int c = wn * 32 + nt * 8 + (lane & 3) * 2;
                    #pragma unroll
                    for (int h = 0; h < 2; h++) {
                        int mm = m + h * 8;
                        float g0 = acc[mt][nt][h * 2], g1 = acc[mt][nt][h * 2 + 1];
                        float u0 = sUp[mm * 64 + c], u1 = sUp[mm * 64 + c + 1];
                        float o0 = g0 / (1.f + expf(-g0)) * u0;
                        float o1 = g1 / (1.f + expf(-g1)) * u1;
                        __nv_bfloat162 hp = __float22bfloat162_rn(make_float2(o0, o1));
                        uint32_t hu = *(uint32_t*)&hp;
                        float r0 = o0 - __uint_as_float(hu << 16);
                        float r1 = o1 - __uint_as_float(hu & 0xFFFF0000u);
                        __nv_bfloat162 lp = __float22bfloat162_rn(make_float2(r0, r1));
                        uint32_t lu = *(uint32_t*)&lp;
                        size_t base = (size_t)(row0 + mm) * IDIM + nb * 64 + c;
                        *(uint32_t*)&g_ih[base] = hu;
                        *(uint32_t*)&g_il[base] = lu;
                    }
                }
        }
    } else {
        #pragma unroll
        for (int mt = 0; mt < 4; mt++)
            #pragma unroll
            for (int nt = 0; nt < 4; nt++) {
                int m = row0 + wm * 64 + mt * 16 + (lane >> 2);
                int c = nb * 128 + wn * 32 + nt * 8 + (lane & 3) * 2;
                *(float2*)&g_y2[(size_t)m * HID + c]       = make_float2(acc[mt][nt][0], acc[mt][nt][1]);
                *(float2*)&g_y2[(size_t)(m + 8) * HID + c] = make_float2(acc[mt][nt][2], acc[mt][nt][3]);
            }
    }
}

// ---------------- combine ----------------
__global__ void combine_kernel(float* __restrict__ out) {
    __shared__ float w[TOPK];
    __shared__ int rows[TOPK];
    int t = blockIdx.x;
    int tid = threadIdx.x;
    if (tid < TOPK) {
        w[tid]    = g_topkw[t * TOPK + tid];
        rows[tid] = g_invperm[t * TOPK + tid];
    }
    __syncthreads();
    float4 acc = make_float4(0.f, 0.f, 0.f, 0.f);
    #pragma unroll
    for (int k = 0; k < TOPK; k++) {
        const float4 v = *(const float4*)&g_y2[(size_t)rows[k] * HID + (tid << 2)];
        float wk = w[k];
        acc.x += wk * v.x; acc.y += wk * v.y; acc.z += wk * v.z; acc.w += wk * v.w;
    }
    *(float4*)(out + (size_t)t * HID + (tid << 2)) = acc;
}

// ---------------- launch ----------------
extern "C" void kernel_launch(void* const* d_in, const int* in_sizes, int n_in,
                              void* d_out, int out_size) {
    const float* x    = (const float*)d_in[0];
    const float* gate = (const float*)d_in[1];
    const float* gup  = (const float*)d_in[2];
    const float* dwn  = (const float*)d_in[3];
    float* out = (float*)d_out;

    cudaFuncSetAttribute(moe_gemm<true>,  cudaFuncAttributeMaxDynamicSharedMemorySize, SMEM_BYTES);
    cudaFuncSetAttribute(moe_gemm<false>, cudaFuncAttributeMaxDynamicSharedMemorySize, SMEM_BYTES);

    // pre-convert inputs / weights to split-bf16 (hi/lo)
    cvt_kernel<<<(int)(((long)NTOK * HID / 8 + 255) / 256), 256>>>(x, 0, (long)NTOK * HID / 8);
    cvt_kernel<<<(int)(((long)NEXP * 2 * IDIM * HID / 8 + 255) / 256), 256>>>(gup, 1, (long)NEXP * 2 * IDIM * HID / 8);
    cvt_kernel<<<(int)(((long)NEXP * HID * IDIM / 8 + 255) / 256), 256>>>(dwn, 2, (long)NEXP * HID * IDIM / 8);

    init_kernel<<<1, 64>>>();
    router_kernel<<<NTOK / RT, 256>>>(x, gate);
    meta_kernel<<<1, 1>>>();
    fill_kernel<<<(MPAD + 255) / 256, 256>>>();
    scatter_kernel<<<(FLAT + 255) / 256, 256>>>();
    moe_gemm<true><<<dim3(MAXTILES, IDIM / 64), 256, SMEM_BYTES>>>();
    moe_gemm<false><<<dim3(MAXTILES, HID / 128), 256, SMEM_BYTES>>>();
    combine_kernel<<<NTOK, 256>>>(out);
}

// round 7
// speedup vs baseline: 1.5260x; 1.5260x over previous
#include <cuda_runtime.h>
#include <cuda_bf16.h>
#include <cstdint>

#define NTOK 4096
#define HID  1024
#define NEXP 64
#define TOPK 8
#define IDIM 768
#define FLAT (NTOK*TOPK)
#define BM   128
#define MPAD 40960
#define MAXTILES 320

// ---------------- scratch ----------------
static __device__ __nv_bfloat16 g_xh[(size_t)NTOK * HID];
static __device__ __nv_bfloat16 g_xl[(size_t)NTOK * HID];
static __device__ __nv_bfloat16 g_wgh[(size_t)NEXP * 2 * IDIM * HID];
static __device__ __nv_bfloat16 g_wgl[(size_t)NEXP * 2 * IDIM * HID];
static __device__ __nv_bfloat16 g_wdh[(size_t)NEXP * HID * IDIM];
static __device__ __nv_bfloat16 g_wdl[(size_t)NEXP * HID * IDIM];
static __device__ __nv_bfloat16 g_ih[(size_t)MPAD * IDIM];
static __device__ __nv_bfloat16 g_il[(size_t)MPAD * IDIM];
static __device__ float g_y2[(size_t)MPAD * HID];
static __device__ float g_topkw[FLAT];
static __device__ int   g_flatexp[FLAT];
static __device__ int   g_invperm[FLAT];
static __device__ int   g_rowtok[MPAD];
static __device__ int   g_counts[NEXP];
static __device__ int   g_ctr[NEXP];
static __device__ int   g_offpad[NEXP];
static __device__ int   g_tile_e[MAXTILES];
static __device__ int   g_tile_r0[MAXTILES];
static __device__ int   g_ntiles;

// ---------------- helpers ----------------
__device__ __forceinline__ uint32_t smem_u32(const void* p) {
    uint32_t a;
    asm("{ .reg .u64 t; cvta.to.shared.u64 t, %1; cvt.u32.u64 %0, t; }" : "=r"(a) : "l"(p));
    return a;
}
#define STS128(a, v) \
    asm volatile("st.shared.v4.b32 [%0], {%1, %2, %3, %4};" \
        :: "r"(a), "r"((v).x), "r"((v).y), "r"((v).z), "r"((v).w) : "memory")

__device__ __forceinline__ void ldsm_x4(uint32_t (&r)[4], uint32_t addr) {
    asm volatile("ldmatrix.sync.aligned.m8n8.x4.shared.b16 {%0,%1,%2,%3}, [%4];"
        : "=r"(r[0]), "=r"(r[1]), "=r"(r[2]), "=r"(r[3]) : "r"(addr));
}
__device__ __forceinline__ void mma16816(float (&d)[4], const uint32_t (&a)[4], const uint32_t (&b)[2]) {
    asm volatile("mma.sync.aligned.m16n8k16.row.col.f32.bf16.bf16.f32 "
        "{%0,%1,%2,%3}, {%4,%5,%6,%7}, {%8,%9}, {%0,%1,%2,%3};"
        : "+f"(d[0]), "+f"(d[1]), "+f"(d[2]), "+f"(d[3])
        : "r"(a[0]), "r"(a[1]), "r"(a[2]), "r"(a[3]), "r"(b[0]), "r"(b[1]));
}

// fp32x8 -> bf16 hi/lo split (prepass only)
__device__ __forceinline__ void cvt8(const float4 f0, const float4 f1, uint4& H, uint4& L) {
    __nv_bfloat162 h;
    h = __float22bfloat162_rn(make_float2(f0.x, f0.y)); uint32_t u0 = *(uint32_t*)&h;
    h = __float22bfloat162_rn(make_float2(f0.z, f0.w)); uint32_t u1 = *(uint32_t*)&h;
    h = __float22bfloat162_rn(make_float2(f1.x, f1.y)); uint32_t u2 = *(uint32_t*)&h;
    h = __float22bfloat162_rn(make_float2(f1.z, f1.w)); uint32_t u3 = *(uint32_t*)&h;
    H = make_uint4(u0, u1, u2, u3);
    float l0 = f0.x - __uint_as_float(u0 << 16);
    float l1 = f0.y - __uint_as_float(u0 & 0xFFFF0000u);
    float l2 = f0.z - __uint_as_float(u1 << 16);
    float l3 = f0.w - __uint_as_float(u1 & 0xFFFF0000u);
    float l4 = f1.x - __uint_as_float(u2 << 16);
    float l5 = f1.y - __uint_as_float(u2 & 0xFFFF0000u);
    float l6 = f1.z - __uint_as_float(u3 << 16);
    float l7 = f1.w - __uint_as_float(u3 & 0xFFFF0000u);
    h = __float22bfloat162_rn(make_float2(l0, l1)); uint32_t v0 = *(uint32_t*)&h;
    h = __float22bfloat162_rn(make_float2(l2, l3)); uint32_t v1 = *(uint32_t*)&h;
    h = __float22bfloat162_rn(make_float2(l4, l5)); uint32_t v2 = *(uint32_t*)&h;
    h = __float22bfloat162_rn(make_float2(l6, l7)); uint32_t v3 = *(uint32_t*)&h;
    L = make_uint4(v0, v1, v2, v3);
}

// swizzled byte offset within a [128 rows][32 bf16] tile (64B rows, 16B chunks)
__device__ __forceinline__ uint32_t swz(int row, int chunk) {
    return (uint32_t)(row * 64 + ((chunk ^ ((row >> 1) & 3)) << 4));
}

// ---------------- conversion prepass ----------------
__global__ void cvt_kernel(const float* __restrict__ src, int mode, long n8) {
    long i = (long)blockIdx.x * 256 + threadIdx.x;
    if (i >= n8) return;
    __nv_bfloat16 *dh, *dl;
    if (mode == 0)      { dh = g_xh;  dl = g_xl;  }
    else if (mode == 1) { dh = g_wgh; dl = g_wgl; }
    else                { dh = g_wdh; dl = g_wdl; }
    float4 f0 = ((const float4*)src)[2 * i];
    float4 f1 = ((const float4*)src)[2 * i + 1];
    uint4 H, L; cvt8(f0, f1, H, L);
    ((uint4*)dh)[i] = H;
    ((uint4*)dl)[i] = L;
}

// ---------------- small kernels ----------------
__global__ void init_kernel() {
    int i = threadIdx.x;
    if (i < NEXP) { g_counts[i] = 0; g_ctr[i] = 0; }
}

#define RT 8
__global__ void router_kernel(const float* __restrict__ x, const float* __restrict__ gate) {
    __shared__ float xs[RT][HID];
    __shared__ float lg[RT][NEXP];
    int t0 = blockIdx.x * RT;
    int tid = threadIdx.x;  // 256
    const float4* xsrc = (const float4*)(x + (size_t)t0 * HID);
    for (int i = tid; i < RT * HID / 4; i += 256) ((float4*)&xs[0][0])[i] = xsrc[i];
    __syncthreads();
    int tt = tid >> 5, lane = tid & 31;
    #pragma unroll
    for (int g = 0; g < 2; g++) {
        int e = g * 32 + lane;
        const float* gp = gate + (size_t)e * HID;
        float s = 0.f;
        #pragma unroll 4
        for (int k = 0; k < HID; k += 4) {
            float4 gv = *(const float4*)(gp + k);
            s += xs[tt][k] * gv.x + xs[tt][k+1] * gv.y + xs[tt][k+2] * gv.z + xs[tt][k+3] * gv.w;
        }
        lg[tt][e] = s;
    }
    __syncthreads();
    if (tid < RT) {
        int t = t0 + tid;
        float mx = lg[tid][0];
        #pragma unroll
        for (int e = 1; e < NEXP; e++) mx = fmaxf(mx, lg[tid][e]);
        unsigned long long taken = 0ull;
        float wsum = 0.f;
        int sel[TOPK]; float wv[TOPK];
        for (int k = 0; k < TOPK; k++) {
            int best = 0; float bv = -1e30f;
            for (int e = 0; e < NEXP; e++) {
                float v = lg[tid][e];
                if (!((taken >> e) & 1ull) && v > bv) { bv = v; best = e; }
            }
            taken |= 1ull << best;
            sel[k] = best;
            float w = expf(lg[tid][best] - mx);
            wv[k] = w; wsum += w;
            atomicAdd(&g_counts[best], 1);
        }
        float inv = 1.f / wsum;
        for (int k = 0; k < TOPK; k++) {
            g_topkw[t * TOPK + k]   = wv[k] * inv;
            g_flatexp[t * TOPK + k] = sel[k];
        }
    }
}

__global__ void meta_kernel() {
    if (threadIdx.x != 0) return;
    int nt = 0, cum = 0;
    for (int e = 0; e < NEXP; e++) {
        g_offpad[e] = cum;
        int c = g_counts[e];
        int t = (c + BM - 1) / BM;
        for (int j = 0; j < t; j++) { g_tile_e[nt] = e; g_tile_r0[nt] = cum + j * BM; nt++; }
        cum += t * BM;
    }
    g_ntiles = nt;
}

__global__ void fill_kernel() {
    int i = blockIdx.x * 256 + threadIdx.x;
    if (i < MPAD) g_rowtok[i] = -1;
}

__global__ void scatter_kernel() {
    int i = blockIdx.x * 256 + threadIdx.x;
    if (i >= FLAT) return;
    int e = g_flatexp[i];
    int dest = g_offpad[e] + atomicAdd(&g_ctr[e], 1);
    g_rowtok[dest] = i >> 3;
    g_invperm[i] = dest;
}

// ---------------- grouped GEMM: R4 structure, pre-split bf16 sources ----------------
// CTA: 256 thr = 8 warps (2x4), tile M=128 x N=128, warp tile 64x32, KC=32.
// LDG.128 prefetch into registers -> STS (no in-loop conversion), 32KB static smem.

template<bool FUSED>
__global__ void __launch_bounds__(256, 1) moe_gemm() {
    constexpr int KDIM = FUSED ? HID : IDIM;   // 1024 / 768
    constexpr int NK   = KDIM / 32;            // 32 / 24
    int tile = blockIdx.x;
    if (tile >= g_ntiles) return;
    int e = g_tile_e[tile], row0 = g_tile_r0[tile], nb = blockIdx.y;

    __shared__ __align__(128) uint16_t sT[4 * 128 * 32];   // 32KB: Ahi|Alo|Bhi|Blo
    uint32_t sb = smem_u32(sT);
    const uint32_t SA_HI = sb, SA_LO = sb + 8192, SB_HI = sb + 16384, SB_LO = sb + 24576;

    int tid = threadIdx.x, lane = tid & 31, wid = tid >> 5;
    int wm = wid >> 2, wn = wid & 3;

    // -------- load-slot mapping: row = tid/4 (+64), chunk = tid%4
    int rA0 = tid >> 2, rA1 = rA0 + 64, ch = tid & 3;
    uint32_t off0 = swz(rA0, ch);
    uint32_t off1 = swz(rA1, ch);

    const __nv_bfloat16* AH = FUSED ? g_xh : g_ih;
    const __nv_bfloat16* AL = FUSED ? g_xl : g_il;
    const __nv_bfloat16* WH = FUSED ? g_wgh : g_wdh;
    const __nv_bfloat16* WL = FUSED ? g_wgl : g_wdl;

    const __nv_bfloat16 *ah0, *al0, *ah1, *al1;
    if (FUSED) {
        int t0 = g_rowtok[row0 + rA0], t1 = g_rowtok[row0 + rA1];
        ah0 = (t0 >= 0) ? AH + (size_t)t0 * HID + ch * 8 : nullptr;
        al0 = (t0 >= 0) ? AL + (size_t)t0 * HID + ch * 8 : nullptr;
        ah1 = (t1 >= 0) ? AH + (size_t)t1 * HID + ch * 8 : nullptr;
        al1 = (t1 >= 0) ? AL + (size_t)t1 * HID + ch * 8 : nullptr;
    } else {
        ah0 = AH + (size_t)(row0 + rA0) * IDIM + ch * 8;
        al0 = AL + (size_t)(row0 + rA0) * IDIM + ch * 8;
        ah1 = AH + (size_t)(row0 + rA1) * IDIM + ch * 8;
        al1 = AL + (size_t)(row0 + rA1) * IDIM + ch * 8;
    }
    size_t wbase = (size_t)e * (size_t)(FUSED ? 2 * IDIM : HID) * KDIM;
    int wr0 = FUSED ? (nb * 64 + rA0) : (nb * 128 + rA0);
    int wr1 = FUSED ? (IDIM + nb * 64 + (rA1 - 64)) : (nb * 128 + rA1);
    const __nv_bfloat16* bh0 = WH + wbase + (size_t)wr0 * KDIM + ch * 8;
    const __nv_bfloat16* bl0 = WL + wbase + (size_t)wr0 * KDIM + ch * 8;
    const __nv_bfloat16* bh1 = WH + wbase + (size_t)wr1 * KDIM + ch * 8;
    const __nv_bfloat16* bl1 = WL + wbase + (size_t)wr1 * KDIM + ch * 8;

    float acc[4][4][4];
    #pragma unroll
    for (int a = 0; a < 4; a++)
        #pragma unroll
        for (int b = 0; b < 4; b++)
            #pragma unroll
            for (int c = 0; c < 4; c++) acc[a][b][c] = 0.f;

    const uint4 Z = make_uint4(0u, 0u, 0u, 0u);
    uint4 pah0, pal0, pah1, pal1, pbh0, pbl0, pbh1, pbl1;
    // prefetch kt = 0
    pah0 = ah0 ? *(const uint4*)(ah0) : Z;  pal0 = al0 ? *(const uint4*)(al0) : Z;
    pah1 = ah1 ? *(const uint4*)(ah1) : Z;  pal1 = al1 ? *(const uint4*)(al1) : Z;
    pbh0 = *(const uint4*)(bh0);            pbl0 = *(const uint4*)(bl0);
    pbh1 = *(const uint4*)(bh1);            pbl1 = *(const uint4*)(bl1);

    #pragma unroll 1
    for (int kt = 0; kt < NK; kt++) {
        __syncthreads();
        STS128(SA_HI + off0, pah0); STS128(SA_LO + off0, pal0);
        STS128(SA_HI + off1, pah1); STS128(SA_LO + off1, pal1);
        STS128(SB_HI + off0, pbh0); STS128(SB_LO + off0, pbl0);
        STS128(SB_HI + off1, pbh1); STS128(SB_LO + off1, pbl1);
        if (kt + 1 < NK) {
            int ko = (kt + 1) * 32;
            pah0 = ah0 ? *(const uint4*)(ah0 + ko) : Z;  pal0 = al0 ? *(const uint4*)(al0 + ko) : Z;
            pah1 = ah1 ? *(const uint4*)(ah1 + ko) : Z;  pal1 = al1 ? *(const uint4*)(al1 + ko) : Z;
            pbh0 = *(const uint4*)(bh0 + ko);            pbl0 = *(const uint4*)(bl0 + ko);
            pbh1 = *(const uint4*)(bh1 + ko);            pbl1 = *(const uint4*)(bl1 + ko);
        }
        __syncthreads();

        #pragma unroll
        for (int kk = 0; kk < 2; kk++) {
            uint32_t aH[4][4], aL[4][4], bH[4][2], bL[4][2];
            #pragma unroll
            for (int mt = 0; mt < 4; mt++) {
                int row = wm * 64 + mt * 16 + (lane & 15);
                uint32_t ad = swz(row, 2 * kk + (lane >> 4));
                ldsm_x4(aH[mt], SA_HI + ad);
                ldsm_x4(aL[mt], SA_LO + ad);
            }
            #pragma unroll
            for (int np = 0; np < 2; np++) {
                int row = wn * 32 + np * 16 + (lane & 7) + ((lane >> 4) << 3);
                uint32_t bd = swz(row, 2 * kk + ((lane >> 3) & 1));
                uint32_t t4[4];
                ldsm_x4(t4, SB_HI + bd);
                bH[2*np][0] = t4[0]; bH[2*np][1] = t4[1];
                bH[2*np+1][0] = t4[2]; bH[2*np+1][1] = t4[3];
                ldsm_x4(t4, SB_LO + bd);
                bL[2*np][0] = t4[0]; bL[2*np][1] = t4[1];
                bL[2*np+1][0] = t4[2]; bL[2*np+1][1] = t4[3];
            }
            #pragma unroll
            for (int mt = 0; mt < 4; mt++)
                #pragma unroll
                for (int nt = 0; nt < 4; nt++) {
                    mma16816(acc[mt][nt], aH[mt], bH[nt]);
                    mma16816(acc[mt][nt], aH[mt], bL[nt]);
                    mma16816(acc[mt][nt], aL[mt], bH[nt]);
                }
        }
    }
    __syncthreads();   // all frag reads done; sT reusable

    if (FUSED) {
        float* sUp = (float*)sT;   // [128][64] f32 = 32KB
        if (wn >= 2) {
            #pragma unroll
            for (int mt = 0; mt < 4; mt++)
                #pragma unroll
                for (int nt = 0; nt < 4; nt++) {
                    int m = wm * 64 + mt * 16 + (lane >> 2);
                    int c = (wn - 2) * 32 + nt * 8 + (lane & 3) * 2;
                    sUp[m * 64 + c]           = acc[mt][nt][0];
                    sUp[m * 64 + c + 1]       = acc[mt][nt][1];
                    sUp[(m + 8) * 64 + c]     = acc[mt][nt][2];
                    sUp[(m + 8) * 64 + c + 1] = acc[mt][nt][3];
                }
        }
        __syncthreads();
        if (wn < 2) {
            #pragma unroll
            for (int mt = 0; mt < 4; mt++)
                #pragma unroll
                for (int nt = 0; nt < 4; nt++) {
                    int m = wm * 64 + mt * 16 + (lane >> 2);
                    int c = wn * 32 + nt * 8 + (lane & 3) * 2;
                    #pragma unroll
                    for (int h = 0; h < 2; h++) {
                        int mm = m + h * 8;
                        float g0 = acc[mt][nt][h * 2], g1 = acc[mt][nt][h * 2 + 1];
                        float u0 = sUp[mm * 64 + c], u1 = sUp[mm * 64 + c + 1];
                        float o0 = g0 / (1.f + expf(-g0)) * u0;
                        float o1 = g1 / (1.f + expf(-g1)) * u1;
                        __nv_bfloat162 hp = __float22bfloat162_rn(make_float2(o0, o1));
                        uint32_t hu = *(uint32_t*)&hp;
                        float r0 = o0 - __uint_as_float(hu << 16);
                        float r1 = o1 - __uint_as_float(hu & 0xFFFF0000u);
                        __nv_bfloat162 lp = __float22bfloat162_rn(make_float2(r0, r1));
                        uint32_t lu = *(uint32_t*)&lp;
                        size_t base = (size_t)(row0 + mm) * IDIM + nb * 64 + c;
                        *(uint32_t*)&g_ih[base] = hu;
                        *(uint32_t*)&g_il[base] = lu;
                    }
                }
        }
    } else {
        #pragma unroll
        for (int mt = 0; mt < 4; mt++)
            #pragma unroll
            for (int nt = 0; nt < 4; nt++) {
                int m = row0 + wm * 64 + mt * 16 + (lane >> 2);
                int c = nb * 128 + wn * 32 + nt * 8 + (lane & 3) * 2;
                *(float2*)&g_y2[(size_t)m * HID + c]       = make_float2(acc[mt][nt][0], acc[mt][nt][1]);
                *(float2*)&g_y2[(size_t)(m + 8) * HID + c] = make_float2(acc[mt][nt][2], acc[mt][nt][3]);
            }
    }
}

// ---------------- combine ----------------
__global__ void combine_kernel(float* __restrict__ out) {
    __shared__ float w[TOPK];
    __shared__ int rows[TOPK];
    int t = blockIdx.x;
    int tid = threadIdx.x;
    if (tid < TOPK) {
        w[tid]    = g_topkw[t * TOPK + tid];
        rows[tid] = g_invperm[t * TOPK + tid];
    }
    __syncthreads();
    float4 acc = make_float4(0.f, 0.f, 0.f, 0.f);
    #pragma unroll
    for (int k = 0; k < TOPK; k++) {
        const float4 v = *(const float4*)&g_y2[(size_t)rows[k] * HID + (tid << 2)];
        float wk = w[k];
        acc.x += wk * v.x; acc.y += wk * v.y; acc.z += wk * v.z; acc.w += wk * v.w;
    }
    *(float4*)(out + (size_t)t * HID + (tid << 2)) = acc;
}

// ---------------- launch ----------------
extern "C" void kernel_launch(void* const* d_in, const int* in_sizes, int n_in,
                              void* d_out, int out_size) {
    const float* x    = (const float*)d_in[0];
    const float* gate = (const float*)d_in[1];
    const float* gup  = (const float*)d_in[2];
    const float* dwn  = (const float*)d_in[3];
    float* out = (float*)d_out;

    // pre-convert inputs / weights to split-bf16 (hi/lo)
    cvt_kernel<<<(int)(((long)NTOK * HID / 8 + 255) / 256), 256>>>(x, 0, (long)NTOK * HID / 8);
    cvt_kernel<<<(int)(((long)NEXP * 2 * IDIM * HID / 8 + 255) / 256), 256>>>(gup, 1, (long)NEXP * 2 * IDIM * HID / 8);
    cvt_kernel<<<(int)(((long)NEXP * HID * IDIM / 8 + 255) / 256), 256>>>(dwn, 2, (long)NEXP * HID * IDIM / 8);

    init_kernel<<<1, 64>>>();
    router_kernel<<<NTOK / RT, 256>>>(x, gate);
    meta_kernel<<<1, 1>>>();
    fill_kernel<<<(MPAD + 255) / 256, 256>>>();
    scatter_kernel<<<(FLAT + 255) / 256, 256>>>();
    moe_gemm<true><<<dim3(MAXTILES, IDIM / 64), 256>>>();
    moe_gemm<false><<<dim3(MAXTILES, HID / 128), 256>>>();
    combine_kernel<<<NTOK, 256>>>(out);
}

// round 8
// speedup vs baseline: 1.7547x; 1.1498x over previous
#include <cuda_runtime.h>
#include <cuda_bf16.h>
#include <cstdint>

#define NTOK 4096
#define HID  1024
#define NEXP 64
#define TOPK 8
#define IDIM 768
#define FLAT (NTOK*TOPK)
#define BM   128
#define MPAD 40960
#define MAXTILES 320

// ---------------- scratch ----------------
static __device__ float g_inter[(size_t)MPAD * IDIM];
static __device__ float g_y2[(size_t)MPAD * HID];
static __device__ float g_topkw[FLAT];
static __device__ int   g_flatexp[FLAT];
static __device__ int   g_invperm[FLAT];
static __device__ int   g_rowtok[MPAD];
static __device__ int   g_counts[NEXP];
static __device__ int   g_ctr[NEXP];
static __device__ int   g_offpad[NEXP];
static __device__ int   g_tile_e[MAXTILES];
static __device__ int   g_tile_r0[MAXTILES];
static __device__ int   g_ntiles;

// ---------------- helpers ----------------
__device__ __forceinline__ uint32_t smem_u32(const void* p) {
    uint32_t a;
    asm("{ .reg .u64 t; cvta.to.shared.u64 t, %1; cvt.u32.u64 %0, t; }" : "=r"(a) : "l"(p));
    return a;
}
#define STS128(a, v) \
    asm volatile("st.shared.v4.b32 [%0], {%1, %2, %3, %4};" \
        :: "r"(a), "r"((v).x), "r"((v).y), "r"((v).z), "r"((v).w) : "memory")

__device__ __forceinline__ void ldsm_x4(uint32_t (&r)[4], uint32_t addr) {
    asm volatile("ldmatrix.sync.aligned.m8n8.x4.shared.b16 {%0,%1,%2,%3}, [%4];"
        : "=r"(r[0]), "=r"(r[1]), "=r"(r[2]), "=r"(r[3]) : "r"(addr));
}
__device__ __forceinline__ void mma16816(float (&d)[4], const uint32_t (&a)[4], const uint32_t (&b)[2]) {
    asm volatile("mma.sync.aligned.m16n8k16.row.col.f32.bf16.bf16.f32 "
        "{%0,%1,%2,%3}, {%4,%5,%6,%7}, {%8,%9}, {%0,%1,%2,%3};"
        : "+f"(d[0]), "+f"(d[1]), "+f"(d[2]), "+f"(d[3])
        : "r"(a[0]), "r"(a[1]), "r"(a[2]), "r"(a[3]), "r"(b[0]), "r"(b[1]));
}

// fp32x8 -> bf16 hi/lo split
__device__ __forceinline__ void cvt8(const float4 f0, const float4 f1, uint4& H, uint4& L) {
    __nv_bfloat162 h;
    h = __float22bfloat162_rn(make_float2(f0.x, f0.y)); uint32_t u0 = *(uint32_t*)&h;
    h = __float22bfloat162_rn(make_float2(f0.z, f0.w)); uint32_t u1 = *(uint32_t*)&h;
    h = __float22bfloat162_rn(make_float2(f1.x, f1.y)); uint32_t u2 = *(uint32_t*)&h;
    h = __float22bfloat162_rn(make_float2(f1.z, f1.w)); uint32_t u3 = *(uint32_t*)&h;
    H = make_uint4(u0, u1, u2, u3);
    float l0 = f0.x - __uint_as_float(u0 << 16);
    float l1 = f0.y - __uint_as_float(u0 & 0xFFFF0000u);
    float l2 = f0.z - __uint_as_float(u1 << 16);
    float l3 = f0.w - __uint_as_float(u1 & 0xFFFF0000u);
    float l4 = f1.x - __uint_as_float(u2 << 16);
    float l5 = f1.y - __uint_as_float(u2 & 0xFFFF0000u);
    float l6 = f1.z - __uint_as_float(u3 << 16);
    float l7 = f1.w - __uint_as_float(u3 & 0xFFFF0000u);
    h = __float22bfloat162_rn(make_float2(l0, l1)); uint32_t v0 = *(uint32_t*)&h;
    h = __float22bfloat162_rn(make_float2(l2, l3)); uint32_t v1 = *(uint32_t*)&h;
    h = __float22bfloat162_rn(make_float2(l4, l5)); uint32_t v2 = *(uint32_t*)&h;
    h = __float22bfloat162_rn(make_float2(l6, l7)); uint32_t v3 = *(uint32_t*)&h;
    L = make_uint4(v0, v1, v2, v3);
}

// swizzled byte offset within a [128 rows][32 bf16] tile (64B rows, 16B chunks)
__device__ __forceinline__ uint32_t swz(int row, int chunk) {
    return (uint32_t)(row * 64 + ((chunk ^ ((row >> 1) & 3)) << 4));
}

// ---------------- small kernels (fused so gemm1 is the 4th launch) ----------------
__global__ void initfill_kernel() {
    int i = blockIdx.x * 256 + threadIdx.x;
    if (i < MPAD) g_rowtok[i] = -1;
    if (i < NEXP) { g_counts[i] = 0; g_ctr[i] = 0; }
}

#define RT 8
__global__ void router_kernel(const float* __restrict__ x, const float* __restrict__ gate) {
    __shared__ float xs[RT][HID];
    __shared__ float lg[RT][NEXP];
    int t0 = blockIdx.x * RT;
    int tid = threadIdx.x;  // 256
    const float4* xsrc = (const float4*)(x + (size_t)t0 * HID);
    for (int i = tid; i < RT * HID / 4; i += 256) ((float4*)&xs[0][0])[i] = xsrc[i];
    __syncthreads();
    int tt = tid >> 5, lane = tid & 31;
    #pragma unroll
    for (int g = 0; g < 2; g++) {
        int e = g * 32 + lane;
        const float* gp = gate + (size_t)e * HID;
        float s = 0.f;
        #pragma unroll 4
        for (int k = 0; k < HID; k += 4) {
            float4 gv = *(const float4*)(gp + k);
            s += xs[tt][k] * gv.x + xs[tt][k+1] * gv.y + xs[tt][k+2] * gv.z + xs[tt][k+3] * gv.w;
        }
        lg[tt][e] = s;
    }
    __syncthreads();
    if (tid < RT) {
        int t = t0 + tid;
        float mx = lg[tid][0];
        #pragma unroll
        for (int e = 1; e < NEXP; e++) mx = fmaxf(mx, lg[tid][e]);
        unsigned long long taken = 0ull;
        float wsum = 0.f;
        int sel[TOPK]; float wv[TOPK];
        for (int k = 0; k < TOPK; k++) {
            int best = 0; float bv = -1e30f;
            for (int e = 0; e < NEXP; e++) {
                float v = lg[tid][e];
                if (!((taken >> e) & 1ull) && v > bv) { bv = v; best = e; }
            }
            taken |= 1ull << best;
            sel[k] = best;
            float w = expf(lg[tid][best] - mx);
            wv[k] = w; wsum += w;
            atomicAdd(&g_counts[best], 1);
        }
        float inv = 1.f / wsum;
        for (int k = 0; k < TOPK; k++) {
            g_topkw[t * TOPK + k]   = wv[k] * inv;
            g_flatexp[t * TOPK + k] = sel[k];
        }
    }
}

// meta (thread 0) + scatter (whole block), single block
__global__ void metascatter_kernel() {
    int tid = threadIdx.x;   // 256
    if (tid == 0) {
        int nt = 0, cum = 0;
        for (int e = 0; e < NEXP; e++) {
            g_offpad[e] = cum;
            int c = g_counts[e];
            int t = (c + BM - 1) / BM;
            for (int j = 0; j < t; j++) { g_tile_e[nt] = e; g_tile_r0[nt] = cum + j * BM; nt++; }
            cum += t * BM;
        }
        g_ntiles = nt;
    }
    __syncthreads();
    for (int i = tid; i < FLAT; i += 256) {
        int e = g_flatexp[i];
        int dest = g_offpad[e] + atomicAdd(&g_ctr[e], 1);
        g_rowtok[dest] = i >> 3;
        g_invperm[i] = dest;
    }
}

// ---------------- grouped GEMM: R4 math, double-buffered smem, 1 sync/K-tile ----------------
// CTA: 256 thr = 8 warps (2x4), tile M=128 x N=128, warp tile 64x32, KC=32.
// Buffer = Ahi|Alo|Bhi|Blo, each [128][32] bf16 = 8KB -> 32KB; 2 buffers = 64KB dynamic.
// Iteration kt: LDG(kt+1) -> compute from buf[kt&1] -> cvt+STS into buf[(kt+1)&1] -> sync.

#define BUF_SZ 32768
#define OFF_ALO 8192
#define OFF_BHI 16384
#define OFF_BLO 24576
#define SMEM_BYTES (2 * BUF_SZ)

template<bool FUSED>
__global__ void __launch_bounds__(256, 1) moe_gemm(const float* __restrict__ Ain,
                                                   const float* __restrict__ W) {
    constexpr int KDIM = FUSED ? HID : IDIM;   // 1024 / 768
    constexpr int NK   = KDIM / 32;            // 32 / 24
    int tile = blockIdx.x;
    if (tile >= g_ntiles) return;
    int e = g_tile_e[tile], row0 = g_tile_r0[tile], nb = blockIdx.y;

    extern __shared__ __align__(128) char smem[];
    uint32_t sb = smem_u32(smem);

    int tid = threadIdx.x, lane = tid & 31, wid = tid >> 5;
    int wm = wid >> 2, wn = wid & 3;

    // -------- load-slot mapping: row = tid/4 (+64), chunk = tid%4
    int rA0 = tid >> 2, rA1 = rA0 + 64, ch = tid & 3;
    uint32_t off0 = swz(rA0, ch);
    uint32_t off1 = swz(rA1, ch);

    const float* A = FUSED ? Ain : (const float*)g_inter;
    const float *aptr0, *aptr1;
    if (FUSED) {
        int t0 = g_rowtok[row0 + rA0], t1 = g_rowtok[row0 + rA1];
        aptr0 = (t0 >= 0) ? A + (size_t)t0 * HID + ch * 8 : nullptr;
        aptr1 = (t1 >= 0) ? A + (size_t)t1 * HID + ch * 8 : nullptr;
    } else {
        aptr0 = A + (size_t)(row0 + rA0) * IDIM + ch * 8;
        aptr1 = A + (size_t)(row0 + rA1) * IDIM + ch * 8;
    }
    const float* Wb = W + (size_t)e * (size_t)(FUSED ? 2 * IDIM : HID) * KDIM;
    int wr0 = FUSED ? (nb * 64 + rA0) : (nb * 128 + rA0);
    int wr1 = FUSED ? (IDIM + nb * 64 + (rA1 - 64)) : (nb * 128 + rA1);
    const float* bptr0 = Wb + (size_t)wr0 * KDIM + ch * 8;
    const float* bptr1 = Wb + (size_t)wr1 * KDIM + ch * 8;

    float acc[4][4][4];
    #pragma unroll
    for (int a = 0; a < 4; a++)
        #pragma unroll
        for (int b = 0; b < 4; b++)
            #pragma unroll
            for (int c = 0; c < 4; c++) acc[a][b][c] = 0.f;

    const float4 Z = make_float4(0.f, 0.f, 0.f, 0.f);
    float4 pa0, pa1, pa2, pa3, pb0, pb1, pb2, pb3;
    // prefetch kt = 0
    pa0 = aptr0 ? *(const float4*)(aptr0)     : Z;
    pa1 = aptr0 ? *(const float4*)(aptr0 + 4) : Z;
    pa2 = aptr1 ? *(const float4*)(aptr1)     : Z;
    pa3 = aptr1 ? *(const float4*)(aptr1 + 4) : Z;
    pb0 = *(const float4*)(bptr0);     pb1 = *(const float4*)(bptr0 + 4);
    pb2 = *(const float4*)(bptr1);     pb3 = *(const float4*)(bptr1 + 4);
    // fill buffer 0
    {
        uint32_t b0 = sb;
        uint4 H, L;
        cvt8(pa0, pa1, H, L); STS128(b0 + off0, H); STS128(b0 + OFF_ALO + off0, L);
        cvt8(pa2, pa3, H, L); STS128(b0 + off1, H); STS128(b0 + OFF_ALO + off1, L);
        cvt8(pb0, pb1, H, L); STS128(b0 + OFF_BHI + off0, H); STS128(b0 + OFF_BLO + off0, L);
        cvt8(pb2, pb3, H, L); STS128(b0 + OFF_BHI + off1, H); STS128(b0 + OFF_BLO + off1, L);
    }
    __syncthreads();

    #pragma unroll 1
    for (int kt = 0; kt < NK; kt++) {
        uint32_t cur = sb + (uint32_t)((kt & 1) * BUF_SZ);
        // issue next-tile LDGs early (latency hidden under compute)
        if (kt + 1 < NK) {
            int ko = (kt + 1) * 32;
            pa0 = aptr0 ? *(const float4*)(aptr0 + ko)     : Z;
            pa1 = aptr0 ? *(const float4*)(aptr0 + ko + 4) : Z;
            pa2 = aptr1 ? *(const float4*)(aptr1 + ko)     : Z;
            pa3 = aptr1 ? *(const float4*)(aptr1 + ko + 4) : Z;
            pb0 = *(const float4*)(bptr0 + ko);     pb1 = *(const float4*)(bptr0 + ko + 4);
            pb2 = *(const float4*)(bptr1 + ko);     pb3 = *(const float4*)(bptr1 + ko + 4);
        }

        #pragma unroll
        for (int kk = 0; kk < 2; kk++) {
            uint32_t aH[4][4], aL[4][4], bH[4][2], bL[4][2];
            #pragma unroll
            for (int mt = 0; mt < 4; mt++) {
                int row = wm * 64 + mt * 16 + (lane & 15);
                uint32_t ad = swz(row, 2 * kk + (lane >> 4));
                ldsm_x4(aH[mt], cur + ad);
                ldsm_x4(aL[mt], cur + OFF_ALO + ad);
            }
            #pragma unroll
            for (int np = 0; np < 2; np++) {
                int row = wn * 32 + np * 16 + (lane & 7) + ((lane >> 4) << 3);
                uint32_t bd = swz(row, 2 * kk + ((lane >> 3) & 1));
                uint32_t t4[4];
                ldsm_x4(t4, cur + OFF_BHI + bd);
                bH[2*np][0] = t4[0]; bH[2*np][1] = t4[1];
                bH[2*np+1][0] = t4[2]; bH[2*np+1][1] = t4[3];
                ldsm_x4(t4, cur + OFF_BLO + bd);
                bL[2*np][0] = t4[0]; bL[2*np][1] = t4[1];
                bL[2*np+1][0] = t4[2]; bL[2*np+1][1] = t4[3];
            }
            #pragma unroll
            for (int mt = 0; mt < 4; mt++)
                #pragma unroll
                for (int nt = 0; nt < 4; nt++) {
                    mma16816(acc[mt][nt], aH[mt], bH[nt]);
                    mma16816(acc[mt][nt], aH[mt], bL[nt]);
                    mma16816(acc[mt][nt], aL[mt], bH[nt]);
                }
        }

        // convert + stage next tile into the other buffer (overlaps other warps' compute)
        if (kt + 1 < NK) {
            uint32_t nxt = sb + (uint32_t)(((kt + 1) & 1) * BUF_SZ);
            uint4 H, L;
            cvt8(pa0, pa1, H, L); STS128(nxt + off0, H); STS128(nxt + OFF_ALO + off0, L);
            cvt8(pa2, pa3, H, L); STS128(nxt + off1, H); STS128(nxt + OFF_ALO + off1, L);
            cvt8(pb0, pb1, H, L); STS128(nxt + OFF_BHI + off0, H); STS128(nxt + OFF_BLO + off0, L);
            cvt8(pb2, pb3, H, L); STS128(nxt + OFF_BHI + off1, H); STS128(nxt + OFF_BLO + off1, L);
        }
        __syncthreads();
    }

    if (FUSED) {
        float* sUp = (float*)smem;   // [128][64] f32 = 32KB
        if (wn >= 2) {
            #pragma unroll
            for (int mt = 0; mt < 4; mt++)
                #pragma unroll
                for (int nt = 0; nt < 4; nt++) {
                    int m = wm * 64 + mt * 16 + (lane >> 2);
                    int c = (wn - 2) * 32 + nt * 8 + (lane & 3) * 2;
                    sUp[m * 64 + c]           = acc[mt][nt][0];
                    sUp[m * 64 + c + 1]       = acc[mt][nt][1];
                    sUp[(m + 8) * 64 + c]     = acc[mt][nt][2];
                    sUp[(m + 8) * 64 + c + 1] = acc[mt][nt][3];
                }
        }
        __syncthreads();
        if (wn < 2) {
            #pragma unroll
            for (int mt = 0; mt < 4; mt++)
                #pragma unroll
                for (int nt = 0; nt < 4; nt++) {
                    int m = wm * 64 + mt * 16 + (lane >> 2);
                    int c = wn * 32 + nt * 8 + (lane & 3) * 2;
                    #pragma unroll
                    for (int h = 0; h < 2; h++) {
                        int mm = m + h * 8;
                        float g0 = acc[mt][nt][h * 2], g1 = acc[mt][nt][h * 2 + 1];
                        float u0 = sUp[mm * 64 + c], u1 = sUp[mm * 64 + c + 1];
                        float2 o;
                        o.x = g0 / (1.f + expf(-g0)) * u0;
                        o.y = g1 / (1.f + expf(-g1)) * u1;
                        *(float2*)&g_inter[(size_t)(row0 + mm) * IDIM + nb * 64 + c] = o;
                    }
                }
        }
    } else {
        #pragma unroll
        for (int mt = 0; mt < 4; mt++)
            #pragma unroll
            for (int nt = 0; nt < 4; nt++) {
                int m = row0 + wm * 64 + mt * 16 + (lane >> 2);
                int c = nb * 128 + wn * 32 + nt * 8 + (lane & 3) * 2;
                *(float2*)&g_y2[(size_t)m * HID + c]       = make_float2(acc[mt][nt][0], acc[mt][nt][1]);
                *(float2*)&g_y2[(size_t)(m + 8) * HID + c] = make_float2(acc[mt][nt][2], acc[mt][nt][3]);
            }
    }
}

// ---------------- combine ----------------
__global__ void combine_kernel(float* __restrict__ out) {
    __shared__ float w[TOPK];
    __shared__ int rows[TOPK];
    int t = blockIdx.x;
    int tid = threadIdx.x;
    if (tid < TOPK) {
        w[tid]    = g_topkw[t * TOPK + tid];
        rows[tid] = g_invperm[t * TOPK + tid];
    }
    __syncthreads();
    float4 acc = make_float4(0.f, 0.f, 0.f, 0.f);
    #pragma unroll
    for (int k = 0; k < TOPK; k++) {
        const float4 v = *(const float4*)&g_y2[(size_t)rows[k] * HID + (tid << 2)];
        float wk = w[k];
        acc.x += wk * v.x; acc.y += wk * v.y; acc.z += wk * v.z; acc.w += wk * v.w;
    }
    *(float4*)(out + (size_t)t * HID + (tid << 2)) = acc;
}

// ---------------- launch ----------------
extern "C" void kernel_launch(void* const* d_in, const int* in_sizes, int n_in,
                              void* d_out, int out_size) {
    const float* x    = (const float*)d_in[0];
    const float* gate = (const float*)d_in[1];
    const float* gup  = (const float*)d_in[2];
    const float* dwn  = (const float*)d_in[3];
    float* out = (float*)d_out;

    cudaFuncSetAttribute(moe_gemm<true>,  cudaFuncAttributeMaxDynamicSharedMemorySize, SMEM_BYTES);
    cudaFuncSetAttribute(moe_gemm<false>, cudaFuncAttributeMaxDynamicSharedMemorySize, SMEM_BYTES);

    initfill_kernel<<<(MPAD + 255) / 256, 256>>>();                     // launch 0
    router_kernel<<<NTOK / RT, 256>>>(x, gate);                         // launch 1
    metascatter_kernel<<<1, 256>>>();                                   // launch 2
    moe_gemm<true><<<dim3(MAXTILES, IDIM / 64), 256, SMEM_BYTES>>>(x, gup);   // launch 3 (profiled)
    moe_gemm<false><<<dim3(MAXTILES, HID / 128), 256, SMEM_BYTES>>>(nullptr, dwn); // launch 4
    combine_kernel<<<NTOK, 256>>>(out);                                 // launch 5
}

// round 9
// speedup vs baseline: 1.8023x; 1.0272x over previous
#include <cuda_runtime.h>
#include <cuda_bf16.h>
#include <cstdint>

#define NTOK 4096
#define HID  1024
#define NEXP 64
#define TOPK 8
#define IDIM 768
#define FLAT (NTOK*TOPK)
#define BM   128
#define MPAD 40960
#define MAXTILES 320

// ---------------- scratch ----------------
static __device__ float g_inter[(size_t)MPAD * IDIM];
static __device__ float g_y2[(size_t)MPAD * HID];
static __device__ float g_topkw[FLAT];
static __device__ int   g_flatexp[FLAT];
static __device__ int   g_invperm[FLAT];
static __device__ int   g_rowtok[MPAD];
static __device__ int   g_counts[NEXP];
static __device__ int   g_ctr[NEXP];
static __device__ int   g_offpad[NEXP];
static __device__ int   g_tile_e[MAXTILES];
static __device__ int   g_tile_r0[MAXTILES];
static __device__ int   g_ntiles;

// ---------------- helpers ----------------
__device__ __forceinline__ uint32_t smem_u32(const void* p) {
    uint32_t a;
    asm("{ .reg .u64 t; cvta.to.shared.u64 t, %1; cvt.u32.u64 %0, t; }" : "=r"(a) : "l"(p));
    return a;
}
#define STS128(a, v) \
    asm volatile("st.shared.v4.b32 [%0], {%1, %2, %3, %4};" \
        :: "r"(a), "r"((v).x), "r"((v).y), "r"((v).z), "r"((v).w) : "memory")

__device__ __forceinline__ void ldsm_x4(uint32_t (&r)[4], uint32_t addr) {
    asm volatile("ldmatrix.sync.aligned.m8n8.x4.shared.b16 {%0,%1,%2,%3}, [%4];"
        : "=r"(r[0]), "=r"(r[1]), "=r"(r[2]), "=r"(r[3]) : "r"(addr));
}
__device__ __forceinline__ void mma16816(float (&d)[4], const uint32_t (&a)[4], const uint32_t (&b)[2]) {
    asm volatile("mma.sync.aligned.m16n8k16.row.col.f32.bf16.bf16.f32 "
        "{%0,%1,%2,%3}, {%4,%5,%6,%7}, {%8,%9}, {%0,%1,%2,%3};"
        : "+f"(d[0]), "+f"(d[1]), "+f"(d[2]), "+f"(d[3])
        : "r"(a[0]), "r"(a[1]), "r"(a[2]), "r"(a[3]), "r"(b[0]), "r"(b[1]));
}

// fp32x8 -> bf16 hi/lo split
__device__ __forceinline__ void cvt8(const float4 f0, const float4 f1, uint4& H, uint4& L) {
    __nv_bfloat162 h;
    h = __float22bfloat162_rn(make_float2(f0.x, f0.y)); uint32_t u0 = *(uint32_t*)&h;
    h = __float22bfloat162_rn(make_float2(f0.z, f0.w)); uint32_t u1 = *(uint32_t*)&h;
    h = __float22bfloat162_rn(make_float2(f1.x, f1.y)); uint32_t u2 = *(uint32_t*)&h;
    h = __float22bfloat162_rn(make_float2(f1.z, f1.w)); uint32_t u3 = *(uint32_t*)&h;
    H = make_uint4(u0, u1, u2, u3);
    float l0 = f0.x - __uint_as_float(u0 << 16);
    float l1 = f0.y - __uint_as_float(u0 & 0xFFFF0000u);
    float l2 = f0.z - __uint_as_float(u1 << 16);
    float l3 = f0.w - __uint_as_float(u1 & 0xFFFF0000u);
    float l4 = f1.x - __uint_as_float(u2 << 16);
    float l5 = f1.y - __uint_as_float(u2 & 0xFFFF0000u);
    float l6 = f1.z - __uint_as_float(u3 << 16);
    float l7 = f1.w - __uint_as_float(u3 & 0xFFFF0000u);
    h = __float22bfloat162_rn(make_float2(l0, l1)); uint32_t v0 = *(uint32_t*)&h;
    h = __float22bfloat162_rn(make_float2(l2, l3)); uint32_t v1 = *(uint32_t*)&h;
    h = __float22bfloat162_rn(make_float2(l4, l5)); uint32_t v2 = *(uint32_t*)&h;
    h = __float22bfloat162_rn(make_float2(l6, l7)); uint32_t v3 = *(uint32_t*)&h;
    L = make_uint4(v0, v1, v2, v3);
}

// swizzled byte offset within a [128 rows][16 bf16] tile (32B rows, 2x16B chunks)
// position within 128B line = (2*row + ch) mod 8; ch ^= (row>>2)&1 makes rows 0..7 distinct.
__device__ __forceinline__ uint32_t swz16(int row, int ch) {
    return (uint32_t)(row * 32 + ((ch ^ ((row >> 2) & 1)) << 4));
}

// ---------------- small kernels (gemm1 stays the 4th launch for ncu) ----------------
__global__ void initfill_kernel() {
    int i = blockIdx.x * 256 + threadIdx.x;
    if (i < MPAD) g_rowtok[i] = -1;
    if (i < NEXP) { g_counts[i] = 0; g_ctr[i] = 0; }
}

#define RT 8
__global__ void router_kernel(const float* __restrict__ x, const float* __restrict__ gate) {
    __shared__ float xs[RT][HID];
    __shared__ float lg[RT][NEXP];
    int t0 = blockIdx.x * RT;
    int tid = threadIdx.x;  // 256
    const float4* xsrc = (const float4*)(x + (size_t)t0 * HID);
    for (int i = tid; i < RT * HID / 4; i += 256) ((float4*)&xs[0][0])[i] = xsrc[i];
    __syncthreads();
    int tt = tid >> 5, lane = tid & 31;
    #pragma unroll
    for (int g = 0; g < 2; g++) {
        int e = g * 32 + lane;
        const float* gp = gate + (size_t)e * HID;
        float s = 0.f;
        #pragma unroll 4
        for (int k = 0; k < HID; k += 4) {
            float4 gv = *(const float4*)(gp + k);
            s += xs[tt][k] * gv.x + xs[tt][k+1] * gv.y + xs[tt][k+2] * gv.z + xs[tt][k+3] * gv.w;
        }
        lg[tt][e] = s;
    }
    __syncthreads();
    if (tid < RT) {
        int t = t0 + tid;
        float mx = lg[tid][0];
        #pragma unroll
        for (int e = 1; e < NEXP; e++) mx = fmaxf(mx, lg[tid][e]);
        unsigned long long taken = 0ull;
        float wsum = 0.f;
        int sel[TOPK]; float wv[TOPK];
        for (int k = 0; k < TOPK; k++) {
            int best = 0; float bv = -1e30f;
            for (int e = 0; e < NEXP; e++) {
                float v = lg[tid][e];
                if (!((taken >> e) & 1ull) && v > bv) { bv = v; best = e; }
            }
            taken |= 1ull << best;
            sel[k] = best;
            float w = expf(lg[tid][best] - mx);
            wv[k] = w; wsum += w;
            atomicAdd(&g_counts[best], 1);
        }
        float inv = 1.f / wsum;
        for (int k = 0; k < TOPK; k++) {
            g_topkw[t * TOPK + k]   = wv[k] * inv;
            g_flatexp[t * TOPK + k] = sel[k];
        }
    }
}

__global__ void metascatter_kernel() {
    int tid = threadIdx.x;   // 256
    if (tid == 0) {
        int nt = 0, cum = 0;
        for (int e = 0; e < NEXP; e++) {
            g_offpad[e] = cum;
            int c = g_counts[e];
            int t = (c + BM - 1) / BM;
            for (int j = 0; j < t; j++) { g_tile_e[nt] = e; g_tile_r0[nt] = cum + j * BM; nt++; }
            cum += t * BM;
        }
        g_ntiles = nt;
    }
    __syncthreads();
    for (int i = tid; i < FLAT; i += 256) {
        int e = g_flatexp[i];
        int dest = g_offpad[e] + atomicAdd(&g_ctr[e], 1);
        g_rowtok[dest] = i >> 3;
        g_invperm[i] = dest;
    }
}

// ---------------- grouped GEMM: KC=16, double-buffer, 2 CTA/SM target ----------------
// CTA: 256 thr = 8 warps (2x4), tile M=128 x N=128, warp tile 64x32, KC=16.
// Buffer = Ahi|Alo|Bhi|Blo, each [128][16] bf16 = 4KB -> 16KB; 2 buffers = 32KB dynamic.
// Iteration kt: LDG(kt+1) -> compute from buf[kt&1] -> cvt+STS into buf[(kt+1)&1] -> sync.

#define BUF_SZ  16384
#define OFF_ALO 4096
#define OFF_BHI 8192
#define OFF_BLO 12288
#define SMEM_BYTES (2 * BUF_SZ)

template<bool FUSED>
__global__ void __launch_bounds__(256, 2) moe_gemm(const float* __restrict__ Ain,
                                                   const float* __restrict__ W) {
    constexpr int KDIM = FUSED ? HID : IDIM;   // 1024 / 768
    constexpr int NK   = KDIM / 16;            // 64 / 48
    int tile = blockIdx.x;
    if (tile >= g_ntiles) return;
    int e = g_tile_e[tile], row0 = g_tile_r0[tile], nb = blockIdx.y;

    extern __shared__ __align__(128) char smem[];
    uint32_t sb = smem_u32(smem);

    int tid = threadIdx.x, lane = tid & 31, wid = tid >> 5;
    int wm = wid >> 2, wn = wid & 3;

    // -------- copy mapping: row = tid/2 (0..127), half = tid&1 (8 fp32 / one 16B bf16 chunk)
    int rA = tid >> 1, chA = tid & 1;
    uint32_t soff = swz16(rA, chA);

    const float* A = FUSED ? Ain : (const float*)g_inter;
    const float* aptr;
    if (FUSED) {
        int t0 = g_rowtok[row0 + rA];
        aptr = (t0 >= 0) ? A + (size_t)t0 * HID + chA * 8 : nullptr;
    } else {
        aptr = A + (size_t)(row0 + rA) * IDIM + chA * 8;
    }
    const float* Wb = W + (size_t)e * (size_t)(FUSED ? 2 * IDIM : HID) * KDIM;
    int wr = FUSED ? ((rA < 64) ? nb * 64 + rA : IDIM + nb * 64 + (rA - 64))
                   : nb * 128 + rA;
    const float* bptr = Wb + (size_t)wr * KDIM + chA * 8;

    float acc[4][4][4];
    #pragma unroll
    for (int a = 0; a < 4; a++)
        #pragma unroll
        for (int b = 0; b < 4; b++)
            #pragma unroll
            for (int c = 0; c < 4; c++) acc[a][b][c] = 0.f;

    const float4 Z = make_float4(0.f, 0.f, 0.f, 0.f);
    float4 pa0, pa1, pb0, pb1;
    // prefetch kt = 0
    pa0 = aptr ? *(const float4*)(aptr)     : Z;
    pa1 = aptr ? *(const float4*)(aptr + 4) : Z;
    pb0 = *(const float4*)(bptr);
    pb1 = *(const float4*)(bptr + 4);
    // fill buffer 0
    {
        uint4 H, L;
        cvt8(pa0, pa1, H, L); STS128(sb + soff, H);           STS128(sb + OFF_ALO + soff, L);
        cvt8(pb0, pb1, H, L); STS128(sb + OFF_BHI + soff, H); STS128(sb + OFF_BLO + soff, L);
    }
    __syncthreads();

    #pragma unroll 1
    for (int kt = 0; kt < NK; kt++) {
        uint32_t cur = sb + (uint32_t)((kt & 1) * BUF_SZ);
        // issue next-tile LDGs early (latency hidden under compute)
        if (kt + 1 < NK) {
            int ko = (kt + 1) * 16;
            pa0 = aptr ? *(const float4*)(aptr + ko)     : Z;
            pa1 = aptr ? *(const float4*)(aptr + ko + 4) : Z;
            pb0 = *(const float4*)(bptr + ko);
            pb1 = *(const float4*)(bptr + ko + 4);
        }

        // -------- compute one k=16 slab
        {
            uint32_t aH[4][4], aL[4][4];
            #pragma unroll
            for (int mt = 0; mt < 4; mt++) {
                int row = wm * 64 + mt * 16 + (lane & 15);
                uint32_t ad = swz16(row, lane >> 4);
                ldsm_x4(aH[mt], cur + ad);
                ldsm_x4(aL[mt], cur + OFF_ALO + ad);
            }
            #pragma unroll
            for (int np = 0; np < 2; np++) {
                int row = wn * 32 + np * 16 + (lane & 7) + ((lane >> 4) << 3);
                uint32_t bd = swz16(row, (lane >> 3) & 1);
                uint32_t tH[4], tL[4];
                ldsm_x4(tH, cur + OFF_BHI + bd);
                ldsm_x4(tL, cur + OFF_BLO + bd);
                uint32_t bH0[2] = {tH[0], tH[1]}, bH1[2] = {tH[2], tH[3]};
                uint32_t bL0[2] = {tL[0], tL[1]}, bL1[2] = {tL[2], tL[3]};
                #pragma unroll
                for (int mt = 0; mt < 4; mt++) {
                    mma16816(acc[mt][2*np],   aH[mt], bH0);
                    mma16816(acc[mt][2*np],   aH[mt], bL0);
                    mma16816(acc[mt][2*np],   aL[mt], bH0);
                    mma16816(acc[mt][2*np+1], aH[mt], bH1);
                    mma16816(acc[mt][2*np+1], aH[mt], bL1);
                    mma16816(acc[mt][2*np+1], aL[mt], bH1);
                }
            }
        }

        // convert + stage next slab into the other buffer
        if (kt + 1 < NK) {
            uint32_t nxt = sb + (uint32_t)(((kt + 1) & 1) * BUF_SZ);
            uint4 H, L;
            cvt8(pa0, pa1, H, L); STS128(nxt + soff, H);           STS128(nxt + OFF_ALO + soff, L);
            cvt8(pb0, pb1, H, L); STS128(nxt + OFF_BHI + soff, H); STS128(nxt + OFF_BLO + soff, L);
        }
        __syncthreads();
    }

    if (FUSED) {
        float* sUp = (float*)smem;   // [128][64] f32 = 32KB (fits exactly)
        if (wn >= 2) {
            #pragma unroll
            for (int mt = 0; mt < 4; mt++)
                #pragma unroll
                for (int nt = 0; nt < 4; nt++) {
                    int m = wm * 64 + mt * 16 + (lane >> 2);
                    int c = (wn - 2) * 32 + nt * 8 + (lane & 3) * 2;
                    sUp[m * 64 + c]           = acc[mt][nt][0];
                    sUp[m * 64 + c + 1]       = acc[mt][nt][1];
                    sUp[(m + 8) * 64 + c]     = acc[mt][nt][2];
                    sUp[(m + 8) * 64 + c + 1] = acc[mt][nt][3];
                }
        }
        __syncthreads();
        if (wn < 2) {
            #pragma unroll
            for (int mt = 0; mt < 4; mt++)
                #pragma unroll
                for (int nt = 0; nt < 4; nt++) {
                    int m = wm * 64 + mt * 16 + (lane >> 2);
                    int c = wn * 32 + nt * 8 + (lane & 3) * 2;
                    #pragma unroll
                    for (int h = 0; h < 2; h++) {
                        int mm = m + h * 8;
                        float g0 = acc[mt][nt][h * 2], g1 = acc[mt][nt][h * 2 + 1];
                        float u0 = sUp[mm * 64 + c], u1 = sUp[mm * 64 + c + 1];
                        float2 o;
                        o.x = g0 / (1.f + expf(-g0)) * u0;
                        o.y = g1 / (1.f + expf(-g1)) * u1;
                        *(float2*)&g_inter[(size_t)(row0 + mm) * IDIM + nb * 64 + c] = o;
                    }
                }
        }
    } else {
        #pragma unroll
        for (int mt = 0; mt < 4; mt++)
            #pragma unroll
            for (int nt = 0; nt < 4; nt++) {
                int m = row0 + wm * 64 + mt * 16 + (lane >> 2);
                int c = nb * 128 + wn * 32 + nt * 8 + (lane & 3) * 2;
                *(float2*)&g_y2[(size_t)m * HID + c]       = make_float2(acc[mt][nt][0], acc[mt][nt][1]);
                *(float2*)&g_y2[(size_t)(m + 8) * HID + c] = make_float2(acc[mt][nt][2], acc[mt][nt][3]);
            }
    }
}

// ---------------- combine ----------------
__global__ void combine_kernel(float* __restrict__ out) {
    __shared__ float w[TOPK];
    __shared__ int rows[TOPK];
    int t = blockIdx.x;
    int tid = threadIdx.x;
    if (tid < TOPK) {
        w[tid]    = g_topkw[t * TOPK + tid];
        rows[tid] = g_invperm[t * TOPK + tid];
    }
    __syncthreads();
    float4 acc = make_float4(0.f, 0.f, 0.f, 0.f);
    #pragma unroll
    for (int k = 0; k < TOPK; k++) {
        const float4 v = *(const float4*)&g_y2[(size_t)rows[k] * HID + (tid << 2)];
        float wk = w[k];
        acc.x += wk * v.x; acc.y += wk * v.y; acc.z += wk * v.z; acc.w += wk * v.w;
    }
    *(float4*)(out + (size_t)t * HID + (tid << 2)) = acc;
}

// ---------------- launch ----------------
extern "C" void kernel_launch(void* const* d_in, const int* in_sizes, int n_in,
                              void* d_out, int out_size) {
    const float* x    = (const float*)d_in[0];
    const float* gate = (const float*)d_in[1];
    const float* gup  = (const float*)d_in[2];
    const float* dwn  = (const float*)d_in[3];
    float* out = (float*)d_out;

    cudaFuncSetAttribute(moe_gemm<true>,  cudaFuncAttributeMaxDynamicSharedMemorySize, SMEM_BYTES);
    cudaFuncSetAttribute(moe_gemm<false>, cudaFuncAttributeMaxDynamicSharedMemorySize, SMEM_BYTES);

    initfill_kernel<<<(MPAD + 255) / 256, 256>>>();                     // launch 0
    router_kernel<<<NTOK / RT, 256>>>(x, gate);                         // launch 1
    metascatter_kernel<<<1, 256>>>();                                   // launch 2
    moe_gemm<true><<<dim3(MAXTILES, IDIM / 64), 256, SMEM_BYTES>>>(x, gup);        // launch 3 (profiled)
    moe_gemm<false><<<dim3(MAXTILES, HID / 128), 256, SMEM_BYTES>>>(nullptr, dwn); // launch 4
    combine_kernel<<<NTOK, 256>>>(out);                                 // launch 5
}